// round 6
// baseline (speedup 1.0000x reference)
#include <cuda_runtime.h>
#include <cuda_bf16.h>
#include <cstdint>
#include <math.h>

#define NN 50000
#define NE 800000
#define HID 128
#define NG 500

// Scratch (device globals: no allocation allowed)
__device__ float g_h[(size_t)NN * HID];              // node features
__device__ float g_P[(size_t)NN * 512];              // [Fdst|Sdst|Fsrc|Ssrc] per node
__device__ float g_agg[(size_t)NN * HID];            // message aggregation
__device__ float g_pool[NG * HID];
__device__ float g_cnt[NG];

// ---------------------------------------------------------------------------
// helpers
// ---------------------------------------------------------------------------
__device__ __forceinline__ uint32_t f2tf32(float x) {
    uint32_t u;
    asm("cvt.rna.tf32.f32 %0, %1;" : "=r"(u) : "f"(x));
    return u;
}

__device__ __forceinline__ void mma_tf32(float c[4], const uint32_t a[4],
                                         const uint32_t b[2]) {
    asm volatile(
        "mma.sync.aligned.m16n8k8.row.col.f32.tf32.tf32.f32 "
        "{%0,%1,%2,%3}, {%4,%5,%6,%7}, {%8,%9}, {%0,%1,%2,%3};"
        : "+f"(c[0]), "+f"(c[1]), "+f"(c[2]), "+f"(c[3])
        : "r"(a[0]), "r"(a[1]), "r"(a[2]), "r"(a[3]), "r"(b[0]), "r"(b[1]));
}

__device__ __forceinline__ void store2(float* p, float x, float y) {
    *(float2*)p = make_float2(x, y);
}

__device__ __forceinline__ float sigmoidf_(float x) {
    return 1.f / (1.f + __expf(-x));
}
__device__ __forceinline__ float softplusf_(float x) {
    return fmaxf(x, 0.f) + log1pf(__expf(-fabsf(x)));
}

// ---------------------------------------------------------------------------
// init: h = emb[x]; zero agg/pool/cnt
// ---------------------------------------------------------------------------
__global__ void k_init(const int* __restrict__ x, const float* __restrict__ emb) {
    int idx = blockIdx.x * blockDim.x + threadIdx.x;  // over NN*32 (float4 units)
    if (idx < NN * 32) {
        int n = idx >> 5, q = idx & 31;
        ((float4*)g_h)[idx] = ((const float4*)emb)[x[n] * 32 + q];
        ((float4*)g_agg)[idx] = make_float4(0.f, 0.f, 0.f, 0.f);
    }
    if (idx < NG * 32) ((float4*)g_pool)[idx] = make_float4(0.f, 0.f, 0.f, 0.f);
    if (idx < NG) g_cnt[idx] = 0.f;
}

// ---------------------------------------------------------------------------
// Node GEMM (tf32 mma m16n8k8): C[M,512], CTA tile 128x128, blockIdx.y=kind.
// ---------------------------------------------------------------------------
#define SSTR 136

__global__ void k_gemm_tc(const float* __restrict__ A, int M,
                          const float* __restrict__ W0, const float* __restrict__ W1,
                          const float* __restrict__ W2, const float* __restrict__ W3,
                          const float* __restrict__ b0, const float* __restrict__ b1,
                          float* __restrict__ out, int ldo)
{
    __shared__ uint32_t Ast[16][SSTR];  // [k][m] transposed
    __shared__ uint32_t Bs[16][SSTR];   // [k][n]
    const int K = 128;

    int kind = blockIdx.y;
    const float* W = (kind == 0) ? W0 : (kind == 1) ? W1 : (kind == 2) ? W2 : W3;
    const float* bias = (kind == 0) ? b0 : (kind == 1) ? b1 : nullptr;
    int cb = kind * 128;
    int row0 = blockIdx.x * 128;
    int tid = threadIdx.x;           // 256 threads = 8 warps
    int lane = tid & 31, wid = tid >> 5;
    int wm = (wid & 1) * 64, wn = (wid >> 1) * 32;
    int gid4 = lane >> 2, tig = lane & 3;

    float acc[4][4][4];
#pragma unroll
    for (int i = 0; i < 4; i++)
#pragma unroll
        for (int j = 0; j < 4; j++)
#pragma unroll
            for (int r = 0; r < 4; r++) acc[i][j][r] = 0.f;

    for (int k0 = 0; k0 < K; k0 += 16) {
#pragma unroll
        for (int i = 0; i < 2; i++) {
            int id = tid * 2 + i;
            int r = id >> 2, q = (id & 3) * 4;
            float4 v = make_float4(0.f, 0.f, 0.f, 0.f);
            int gr = row0 + r;
            if (gr < M) v = *(const float4*)(A + (size_t)gr * K + k0 + q);
            Ast[q + 0][r] = f2tf32(v.x);
            Ast[q + 1][r] = f2tf32(v.y);
            Ast[q + 2][r] = f2tf32(v.z);
            Ast[q + 3][r] = f2tf32(v.w);
        }
#pragma unroll
        for (int i = 0; i < 2; i++) {
            int id = tid * 2 + i;
            int kk = id >> 5, n4 = (id & 31) * 4;
            float4 v = *(const float4*)(W + (size_t)(k0 + kk) * 128 + n4);
            Bs[kk][n4 + 0] = f2tf32(v.x);
            Bs[kk][n4 + 1] = f2tf32(v.y);
            Bs[kk][n4 + 2] = f2tf32(v.z);
            Bs[kk][n4 + 3] = f2tf32(v.w);
        }
        __syncthreads();

#pragma unroll
        for (int kk = 0; kk < 16; kk += 8) {
            uint32_t a[4][4], b[4][2];
#pragma unroll
            for (int i = 0; i < 4; i++) {
                int m0 = wm + i * 16 + gid4;
                a[i][0] = Ast[kk + tig][m0];
                a[i][1] = Ast[kk + tig][m0 + 8];
                a[i][2] = Ast[kk + tig + 4][m0];
                a[i][3] = Ast[kk + tig + 4][m0 + 8];
            }
#pragma unroll
            for (int j = 0; j < 4; j++) {
                int n0 = wn + j * 8 + gid4;
                b[j][0] = Bs[kk + tig][n0];
                b[j][1] = Bs[kk + tig + 4][n0];
            }
#pragma unroll
            for (int i = 0; i < 4; i++)
#pragma unroll
                for (int j = 0; j < 4; j++) mma_tf32(acc[i][j], a[i], b[j]);
        }
        __syncthreads();
    }

#pragma unroll
    for (int j = 0; j < 4; j++) {
        int cl = wn + j * 8 + 2 * tig;
        float bx = 0.f, by = 0.f;
        if (bias) { bx = bias[cl]; by = bias[cl + 1]; }
#pragma unroll
        for (int i = 0; i < 4; i++) {
            int r0 = row0 + wm + i * 16 + gid4;
            if (r0 < M)
                store2(out + (size_t)r0 * ldo + cb + cl, acc[i][j][0] + bx, acc[i][j][1] + by);
            if (r0 + 8 < M)
                store2(out + (size_t)(r0 + 8) * ldo + cb + cl, acc[i][j][2] + bx, acc[i][j][3] + by);
        }
    }
}

// ---------------------------------------------------------------------------
// Fused edge kernel: per CTA (256 thr), 64 edges.
//  Phase 1: Eproj[64x256] = ea[tile,32] @ [Wf_e | Ws_e] via tf32 mma -> smem bf16
//  Phase 2: warp-per-edge: z = P[dst] + P[src] + Eproj; msg; red.v4 to agg[dst]
// ---------------------------------------------------------------------------
#define TILE_E 64
#define ASTR2 72    // 72 % 32 == 8 -> conflict-free a-frag loads
#define BSTR2 264   // 264 % 32 == 8 -> conflict-free b-frag loads
#define ESTR 264    // bf16 elements per Eproj row (132 words % 32 == 4-safe pattern)

#define SMEM_FUSED (32 * ASTR2 * 4 + 32 * BSTR2 * 4 + TILE_E * ESTR * 2)

extern __shared__ unsigned char s_raw[];

__global__ void __launch_bounds__(256, 2)
k_fused(const int* __restrict__ ei, const float* __restrict__ ea,
        const float* __restrict__ Wfe, const float* __restrict__ Wse)
{
    uint32_t* Ast = (uint32_t*)s_raw;                     // [32][ASTR2]
    uint32_t* Bs  = Ast + 32 * ASTR2;                     // [32][BSTR2]
    __nv_bfloat16* Ep = (__nv_bfloat16*)(Bs + 32 * BSTR2);// [64][ESTR]

    int e0 = blockIdx.x * TILE_E;
    int tid = threadIdx.x, lane = tid & 31, wid = tid >> 5;
    int gid4 = lane >> 2, tig = lane & 3;

    // ---- load A: ea[e0 .. e0+63][0:32] transposed -> Ast[k][m] ----
#pragma unroll
    for (int i = 0; i < 2; i++) {
        int id = tid * 2 + i;            // 0..511
        int r = id >> 3, q = (id & 7) * 4;
        float4 v = *(const float4*)(ea + (size_t)(e0 + r) * 32 + q);
        Ast[(q + 0) * ASTR2 + r] = f2tf32(v.x);
        Ast[(q + 1) * ASTR2 + r] = f2tf32(v.y);
        Ast[(q + 2) * ASTR2 + r] = f2tf32(v.z);
        Ast[(q + 3) * ASTR2 + r] = f2tf32(v.w);
    }
    // ---- load B: [32 x 256] = Wf_e cols | Ws_e cols ----
#pragma unroll
    for (int i = 0; i < 8; i++) {
        int id = tid + i * 256;          // 0..2047
        int kk = id >> 6, n4 = (id & 63) * 4;
        const float* src = (n4 < 128) ? (Wfe + kk * 128 + n4)
                                      : (Wse + kk * 128 + (n4 - 128));
        float4 v = *(const float4*)src;
        uint32_t* d = &Bs[kk * BSTR2 + n4];
        d[0] = f2tf32(v.x); d[1] = f2tf32(v.y);
        d[2] = f2tf32(v.z); d[3] = f2tf32(v.w);
    }
    __syncthreads();

    // ---- mma: M=64 (2 warps), N=256 (4 warp cols of 64), K=32 ----
    {
        int wm = (wid & 1) * 32, wn = (wid >> 1) * 64;
        float acc[2][8][4];
#pragma unroll
        for (int i = 0; i < 2; i++)
#pragma unroll
            for (int j = 0; j < 8; j++)
#pragma unroll
                for (int r = 0; r < 4; r++) acc[i][j][r] = 0.f;

#pragma unroll
        for (int kk = 0; kk < 32; kk += 8) {
            uint32_t a[2][4], b[8][2];
#pragma unroll
            for (int i = 0; i < 2; i++) {
                int m0 = wm + i * 16 + gid4;
                a[i][0] = Ast[(kk + tig) * ASTR2 + m0];
                a[i][1] = Ast[(kk + tig) * ASTR2 + m0 + 8];
                a[i][2] = Ast[(kk + tig + 4) * ASTR2 + m0];
                a[i][3] = Ast[(kk + tig + 4) * ASTR2 + m0 + 8];
            }
#pragma unroll
            for (int j = 0; j < 8; j++) {
                int n0 = wn + j * 8 + gid4;
                b[j][0] = Bs[(kk + tig) * BSTR2 + n0];
                b[j][1] = Bs[(kk + tig + 4) * BSTR2 + n0];
            }
#pragma unroll
            for (int i = 0; i < 2; i++)
#pragma unroll
                for (int j = 0; j < 8; j++) mma_tf32(acc[i][j], a[i], b[j]);
        }

        // write Eproj (bf16x2)
#pragma unroll
        for (int j = 0; j < 8; j++) {
            int cl = wn + j * 8 + 2 * tig;
#pragma unroll
            for (int i = 0; i < 2; i++) {
                int row = wm + i * 16 + gid4;
                *(__nv_bfloat162*)&Ep[row * ESTR + cl] =
                    __floats2bfloat162_rn(acc[i][j][0], acc[i][j][1]);
                *(__nv_bfloat162*)&Ep[(row + 8) * ESTR + cl] =
                    __floats2bfloat162_rn(acc[i][j][2], acc[i][j][3]);
            }
        }
    }
    __syncthreads();

    // ---- edge phase: warp wid handles edges wid*8 .. wid*8+7 ----
#pragma unroll 2
    for (int t = 0; t < 8; t++) {
        int el = wid * 8 + t;
        int e = e0 + el;
        int src = ei[e];
        int dst = ei[NE + e];

        const float4* pd = (const float4*)(g_P + (size_t)dst * 512);
        const float4* ps = (const float4*)(g_P + (size_t)src * 512 + 256);

        float4 f0 = pd[lane], f1 = ps[lane];
        float4 s0 = pd[lane + 32], s1 = ps[lane + 32];

        uint2 euf = *(const uint2*)&Ep[el * ESTR + lane * 4];
        uint2 eus = *(const uint2*)&Ep[el * ESTR + 128 + lane * 4];
        float2 ef0 = __bfloat1622float2(*(__nv_bfloat162*)&euf.x);
        float2 ef1 = __bfloat1622float2(*(__nv_bfloat162*)&euf.y);
        float2 es0 = __bfloat1622float2(*(__nv_bfloat162*)&eus.x);
        float2 es1 = __bfloat1622float2(*(__nv_bfloat162*)&eus.y);

        float zf0 = f0.x + f1.x + ef0.x, zf1 = f0.y + f1.y + ef0.y;
        float zf2 = f0.z + f1.z + ef1.x, zf3 = f0.w + f1.w + ef1.y;
        float zs0 = s0.x + s1.x + es0.x, zs1 = s0.y + s1.y + es0.y;
        float zs2 = s0.z + s1.z + es1.x, zs3 = s0.w + s1.w + es1.y;

        float m0 = sigmoidf_(zf0) * softplusf_(zs0);
        float m1 = sigmoidf_(zf1) * softplusf_(zs1);
        float m2 = sigmoidf_(zf2) * softplusf_(zs2);
        float m3 = sigmoidf_(zf3) * softplusf_(zs3);

        float* ag = g_agg + (size_t)dst * HID + lane * 4;
        asm volatile("red.global.add.v4.f32 [%0], {%1,%2,%3,%4};"
                     :: "l"(ag), "f"(m0), "f"(m1), "f"(m2), "f"(m3) : "memory");
    }
}

// ---------------------------------------------------------------------------
// h = relu(h + agg); agg = 0
// ---------------------------------------------------------------------------
__global__ void k_update() {
    int idx = blockIdx.x * blockDim.x + threadIdx.x;  // NN*32
    if (idx >= NN * 32) return;
    float4 h = ((float4*)g_h)[idx];
    float4 a = ((float4*)g_agg)[idx];
    h.x = fmaxf(h.x + a.x, 0.f);
    h.y = fmaxf(h.y + a.y, 0.f);
    h.z = fmaxf(h.z + a.z, 0.f);
    h.w = fmaxf(h.w + a.w, 0.f);
    ((float4*)g_h)[idx] = h;
    ((float4*)g_agg)[idx] = make_float4(0.f, 0.f, 0.f, 0.f);
}

// ---------------------------------------------------------------------------
// pool: atomic sums per graph + counts
// ---------------------------------------------------------------------------
__global__ void k_pool(const int* __restrict__ batch) {
    int idx = blockIdx.x * blockDim.x + threadIdx.x;  // NN*32
    if (idx >= NN * 32) return;
    int n = idx >> 5, q = idx & 31;
    int g = batch[n];
    float4 v = ((float4*)g_h)[idx];
    float* p = g_pool + (size_t)g * HID + q * 4;
    asm volatile("red.global.add.v4.f32 [%0], {%1,%2,%3,%4};"
                 :: "l"(p), "f"(v.x), "f"(v.y), "f"(v.z), "f"(v.w) : "memory");
    if (q == 0) atomicAdd(&g_cnt[g], 1.f);
}

// ---------------------------------------------------------------------------
// final: out[g] = (pool[g]/max(cnt,1)) @ Wlin + blin   (block per graph)
// ---------------------------------------------------------------------------
__global__ void k_final(const float* __restrict__ Wlin, const float* __restrict__ blin,
                        float* __restrict__ out) {
    __shared__ float p[HID];
    int g = blockIdx.x, t = threadIdx.x;
    float c = fmaxf(g_cnt[g], 1.f);
    p[t] = g_pool[g * HID + t] / c;
    __syncthreads();
    float acc = blin[t];
#pragma unroll 8
    for (int k = 0; k < HID; k++) acc += p[k] * Wlin[k * HID + t];
    out[g * HID + t] = acc;
}

// ---------------------------------------------------------------------------
extern "C" void kernel_launch(void* const* d_in, const int* in_sizes, int n_in,
                              void* d_out, int out_size) {
    const int*   x    = (const int*)d_in[0];
    const int*   ei   = (const int*)d_in[1];
    const float* ea   = (const float*)d_in[2];
    const int*   batch= (const int*)d_in[3];
    const float* emb  = (const float*)d_in[4];
    const float* Wlin = (const float*)d_in[17];
    const float* blin = (const float*)d_in[18];

    float* out = (float*)d_out;

    float* Pp;  cudaGetSymbolAddress((void**)&Pp, g_P);
    float* hp;  cudaGetSymbolAddress((void**)&hp, g_h);

    static bool attr_done = false;
    if (!attr_done) {
        cudaFuncSetAttribute(k_fused, cudaFuncAttributeMaxDynamicSharedMemorySize,
                             SMEM_FUSED);
        attr_done = true;
    }

    // init
    {
        int total = NN * 32;
        k_init<<<(total + 255) / 256, 256>>>(x, emb);
    }

    for (int l = 0; l < 3; l++) {
        const float* Wf = (const float*)d_in[5 + 4 * l];
        const float* bf = (const float*)d_in[6 + 4 * l];
        const float* Ws = (const float*)d_in[7 + 4 * l];
        const float* bs = (const float*)d_in[8 + 4 * l];

        // Node projections: P[n] = [h@WfA+bf | h@WsA+bs | h@WfB | h@WsB]
        {
            dim3 grid((NN + 127) / 128, 4);
            k_gemm_tc<<<grid, 256>>>(hp, NN,
                                     Wf, Ws, Wf + 128 * 128, Ws + 128 * 128,
                                     bf, bs, Pp, 512);
        }
        // Fused edge-attr projection + message + scatter
        {
            k_fused<<<NE / TILE_E, 256, SMEM_FUSED>>>(ei, ea,
                                                      Wf + 256 * 128, Ws + 256 * 128);
        }
        // h = relu(h + agg); agg = 0
        {
            int total = NN * 32;
            k_update<<<(total + 255) / 256, 256>>>();
        }
    }

    // pooling
    {
        int total = NN * 32;
        k_pool<<<(total + 255) / 256, 256>>>(batch);
    }
    // final linear
    k_final<<<NG, HID>>>(Wlin, blin, out);

    (void)in_sizes; (void)n_in; (void)out_size;
}

// round 7
// speedup vs baseline: 1.0994x; 1.0994x over previous
#include <cuda_runtime.h>
#include <cuda_fp16.h>
#include <cstdint>
#include <math.h>

#define NN 50000
#define NE 800000
#define HID 128
#define NG 500

// Scratch (device globals: no allocation allowed)
__device__ float g_h[(size_t)NN * HID];              // node features
__device__ __half g_Ph[(size_t)NN * 512];            // [Fdst|Sdst|Fsrc|Ssrc] per node (fp16)
__device__ float g_agg[(size_t)NN * HID];            // message aggregation
__device__ float g_pool[NG * HID];
__device__ float g_cnt[NG];

// ---------------------------------------------------------------------------
// helpers
// ---------------------------------------------------------------------------
__device__ __forceinline__ uint32_t f2tf32(float x) {
    uint32_t u;
    asm("cvt.rna.tf32.f32 %0, %1;" : "=r"(u) : "f"(x));
    return u;
}

__device__ __forceinline__ void mma_tf32(float c[4], const uint32_t a[4],
                                         const uint32_t b[2]) {
    asm volatile(
        "mma.sync.aligned.m16n8k8.row.col.f32.tf32.tf32.f32 "
        "{%0,%1,%2,%3}, {%4,%5,%6,%7}, {%8,%9}, {%0,%1,%2,%3};"
        : "+f"(c[0]), "+f"(c[1]), "+f"(c[2]), "+f"(c[3])
        : "r"(a[0]), "r"(a[1]), "r"(a[2]), "r"(a[3]), "r"(b[0]), "r"(b[1]));
}

__device__ __forceinline__ float sigmoidf_(float x) {
    return 1.f / (1.f + __expf(-x));
}
__device__ __forceinline__ float softplusf_(float x) {
    return fmaxf(x, 0.f) + log1pf(__expf(-fabsf(x)));
}

// ---------------------------------------------------------------------------
// init: h = emb[x]; zero agg/pool/cnt
// ---------------------------------------------------------------------------
__global__ void k_init(const int* __restrict__ x, const float* __restrict__ emb) {
    int idx = blockIdx.x * blockDim.x + threadIdx.x;  // over NN*32 (float4 units)
    if (idx < NN * 32) {
        int n = idx >> 5, q = idx & 31;
        ((float4*)g_h)[idx] = ((const float4*)emb)[x[n] * 32 + q];
        ((float4*)g_agg)[idx] = make_float4(0.f, 0.f, 0.f, 0.f);
    }
    if (idx < NG * 32) ((float4*)g_pool)[idx] = make_float4(0.f, 0.f, 0.f, 0.f);
    if (idx < NG) g_cnt[idx] = 0.f;
}

// ---------------------------------------------------------------------------
// Node GEMM (tf32 mma m16n8k8): P[M,512] fp16 out, CTA tile 128x128,
// blockIdx.y = kind (0..3) selects weight slice + optional bias.
// ---------------------------------------------------------------------------
#define SSTR 136

__global__ void k_gemm_tc(const float* __restrict__ A, int M,
                          const float* __restrict__ W0, const float* __restrict__ W1,
                          const float* __restrict__ W2, const float* __restrict__ W3,
                          const float* __restrict__ b0, const float* __restrict__ b1,
                          __half* __restrict__ out, int ldo)
{
    __shared__ uint32_t Ast[16][SSTR];  // [k][m] transposed
    __shared__ uint32_t Bs[16][SSTR];   // [k][n]
    const int K = 128;

    int kind = blockIdx.y;
    const float* W = (kind == 0) ? W0 : (kind == 1) ? W1 : (kind == 2) ? W2 : W3;
    const float* bias = (kind == 0) ? b0 : (kind == 1) ? b1 : nullptr;
    int cb = kind * 128;
    int row0 = blockIdx.x * 128;
    int tid = threadIdx.x;           // 256 threads = 8 warps
    int lane = tid & 31, wid = tid >> 5;
    int wm = (wid & 1) * 64, wn = (wid >> 1) * 32;
    int gid4 = lane >> 2, tig = lane & 3;

    float acc[4][4][4];
#pragma unroll
    for (int i = 0; i < 4; i++)
#pragma unroll
        for (int j = 0; j < 4; j++)
#pragma unroll
            for (int r = 0; r < 4; r++) acc[i][j][r] = 0.f;

    for (int k0 = 0; k0 < K; k0 += 16) {
#pragma unroll
        for (int i = 0; i < 2; i++) {
            int id = tid * 2 + i;
            int r = id >> 2, q = (id & 3) * 4;
            float4 v = make_float4(0.f, 0.f, 0.f, 0.f);
            int gr = row0 + r;
            if (gr < M) v = *(const float4*)(A + (size_t)gr * K + k0 + q);
            Ast[q + 0][r] = f2tf32(v.x);
            Ast[q + 1][r] = f2tf32(v.y);
            Ast[q + 2][r] = f2tf32(v.z);
            Ast[q + 3][r] = f2tf32(v.w);
        }
#pragma unroll
        for (int i = 0; i < 2; i++) {
            int id = tid * 2 + i;
            int kk = id >> 5, n4 = (id & 31) * 4;
            float4 v = *(const float4*)(W + (size_t)(k0 + kk) * 128 + n4);
            Bs[kk][n4 + 0] = f2tf32(v.x);
            Bs[kk][n4 + 1] = f2tf32(v.y);
            Bs[kk][n4 + 2] = f2tf32(v.z);
            Bs[kk][n4 + 3] = f2tf32(v.w);
        }
        __syncthreads();

#pragma unroll
        for (int kk = 0; kk < 16; kk += 8) {
            uint32_t a[4][4], b[4][2];
#pragma unroll
            for (int i = 0; i < 4; i++) {
                int m0 = wm + i * 16 + gid4;
                a[i][0] = Ast[kk + tig][m0];
                a[i][1] = Ast[kk + tig][m0 + 8];
                a[i][2] = Ast[kk + tig + 4][m0];
                a[i][3] = Ast[kk + tig + 4][m0 + 8];
            }
#pragma unroll
            for (int j = 0; j < 4; j++) {
                int n0 = wn + j * 8 + gid4;
                b[j][0] = Bs[kk + tig][n0];
                b[j][1] = Bs[kk + tig + 4][n0];
            }
#pragma unroll
            for (int i = 0; i < 4; i++)
#pragma unroll
                for (int j = 0; j < 4; j++) mma_tf32(acc[i][j], a[i], b[j]);
        }
        __syncthreads();
    }

#pragma unroll
    for (int j = 0; j < 4; j++) {
        int cl = wn + j * 8 + 2 * tig;
        float bx = 0.f, by = 0.f;
        if (bias) { bx = bias[cl]; by = bias[cl + 1]; }
#pragma unroll
        for (int i = 0; i < 4; i++) {
            int r0 = row0 + wm + i * 16 + gid4;
            if (r0 < M)
                *(__half2*)(out + (size_t)r0 * ldo + cb + cl) =
                    __floats2half2_rn(acc[i][j][0] + bx, acc[i][j][1] + by);
            if (r0 + 8 < M)
                *(__half2*)(out + (size_t)(r0 + 8) * ldo + cb + cl) =
                    __floats2half2_rn(acc[i][j][2] + bx, acc[i][j][3] + by);
        }
    }
}

// ---------------------------------------------------------------------------
// Fused edge kernel: per CTA (256 thr), 64 edges.
//  Phase 1: Eproj[64x256] = ea[tile,32] @ [Wf_e | Ws_e] via tf32 mma -> smem fp16
//  Phase 2: warp-per-edge: z = Ph[dst] + Ph[src] + Eproj; msg; red.v4 to agg[dst]
// ---------------------------------------------------------------------------
#define TILE_E 64
#define ASTR2 72
#define BSTR2 264
#define ESTR 264

#define SMEM_FUSED (32 * ASTR2 * 4 + 32 * BSTR2 * 4 + TILE_E * ESTR * 2)

extern __shared__ unsigned char s_raw[];

__global__ void __launch_bounds__(256, 2)
k_fused(const int* __restrict__ ei, const float* __restrict__ ea,
        const float* __restrict__ Wfe, const float* __restrict__ Wse)
{
    uint32_t* Ast = (uint32_t*)s_raw;                 // [32][ASTR2]
    uint32_t* Bs  = Ast + 32 * ASTR2;                 // [32][BSTR2]
    __half* Ep = (__half*)(Bs + 32 * BSTR2);          // [64][ESTR]

    int e0 = blockIdx.x * TILE_E;
    int tid = threadIdx.x, lane = tid & 31, wid = tid >> 5;
    int gid4 = lane >> 2, tig = lane & 3;

    // ---- load A: ea[e0 .. e0+63][0:32] transposed -> Ast[k][m] ----
#pragma unroll
    for (int i = 0; i < 2; i++) {
        int id = tid * 2 + i;            // 0..511
        int r = id >> 3, q = (id & 7) * 4;
        float4 v = *(const float4*)(ea + (size_t)(e0 + r) * 32 + q);
        Ast[(q + 0) * ASTR2 + r] = f2tf32(v.x);
        Ast[(q + 1) * ASTR2 + r] = f2tf32(v.y);
        Ast[(q + 2) * ASTR2 + r] = f2tf32(v.z);
        Ast[(q + 3) * ASTR2 + r] = f2tf32(v.w);
    }
    // ---- load B: [32 x 256] = Wf_e cols | Ws_e cols ----
#pragma unroll
    for (int i = 0; i < 8; i++) {
        int id = tid + i * 256;          // 0..2047
        int kk = id >> 6, n4 = (id & 63) * 4;
        const float* src = (n4 < 128) ? (Wfe + kk * 128 + n4)
                                      : (Wse + kk * 128 + (n4 - 128));
        float4 v = *(const float4*)src;
        uint32_t* d = &Bs[kk * BSTR2 + n4];
        d[0] = f2tf32(v.x); d[1] = f2tf32(v.y);
        d[2] = f2tf32(v.z); d[3] = f2tf32(v.w);
    }
    __syncthreads();

    // ---- mma: M=64 (2 warp rows), N=256 (4 warp cols of 64), K=32 ----
    {
        int wm = (wid & 1) * 32, wn = (wid >> 1) * 64;
        float acc[2][8][4];
#pragma unroll
        for (int i = 0; i < 2; i++)
#pragma unroll
            for (int j = 0; j < 8; j++)
#pragma unroll
                for (int r = 0; r < 4; r++) acc[i][j][r] = 0.f;

#pragma unroll
        for (int kk = 0; kk < 32; kk += 8) {
            uint32_t a[2][4], b[8][2];
#pragma unroll
            for (int i = 0; i < 2; i++) {
                int m0 = wm + i * 16 + gid4;
                a[i][0] = Ast[(kk + tig) * ASTR2 + m0];
                a[i][1] = Ast[(kk + tig) * ASTR2 + m0 + 8];
                a[i][2] = Ast[(kk + tig + 4) * ASTR2 + m0];
                a[i][3] = Ast[(kk + tig + 4) * ASTR2 + m0 + 8];
            }
#pragma unroll
            for (int j = 0; j < 8; j++) {
                int n0 = wn + j * 8 + gid4;
                b[j][0] = Bs[(kk + tig) * BSTR2 + n0];
                b[j][1] = Bs[(kk + tig + 4) * BSTR2 + n0];
            }
#pragma unroll
            for (int i = 0; i < 2; i++)
#pragma unroll
                for (int j = 0; j < 8; j++) mma_tf32(acc[i][j], a[i], b[j]);
        }

        // write Eproj (fp16x2)
#pragma unroll
        for (int j = 0; j < 8; j++) {
            int cl = wn + j * 8 + 2 * tig;
#pragma unroll
            for (int i = 0; i < 2; i++) {
                int row = wm + i * 16 + gid4;
                *(__half2*)&Ep[row * ESTR + cl] =
                    __floats2half2_rn(acc[i][j][0], acc[i][j][1]);
                *(__half2*)&Ep[(row + 8) * ESTR + cl] =
                    __floats2half2_rn(acc[i][j][2], acc[i][j][3]);
            }
        }
    }
    __syncthreads();

    // ---- edge phase: warp wid handles edges wid*8 .. wid*8+7 ----
#pragma unroll 2
    for (int t = 0; t < 8; t++) {
        int el = wid * 8 + t;
        int e = e0 + el;
        int src = ei[e];
        int dst = ei[NE + e];

        // uint2 = 4 halves per lane; layout in halves:
        // [0:128)=Fdst [128:256)=Sdst [256:384)=Fsrc [384:512)=Ssrc
        const uint2* pd = (const uint2*)(g_Ph + (size_t)dst * 512);
        const uint2* ps = (const uint2*)(g_Ph + (size_t)src * 512);

        uint2 fdu = pd[lane],      sdu = pd[lane + 32];
        uint2 fsu = ps[lane + 64], ssu = ps[lane + 96];

        float2 fd0 = __half22float2(*(__half2*)&fdu.x);
        float2 fd1 = __half22float2(*(__half2*)&fdu.y);
        float2 sd0 = __half22float2(*(__half2*)&sdu.x);
        float2 sd1 = __half22float2(*(__half2*)&sdu.y);
        float2 fs0 = __half22float2(*(__half2*)&fsu.x);
        float2 fs1 = __half22float2(*(__half2*)&fsu.y);
        float2 ss0 = __half22float2(*(__half2*)&ssu.x);
        float2 ss1 = __half22float2(*(__half2*)&ssu.y);

        uint2 euf = *(const uint2*)&Ep[el * ESTR + lane * 4];
        uint2 eus = *(const uint2*)&Ep[el * ESTR + 128 + lane * 4];
        float2 ef0 = __half22float2(*(__half2*)&euf.x);
        float2 ef1 = __half22float2(*(__half2*)&euf.y);
        float2 es0 = __half22float2(*(__half2*)&eus.x);
        float2 es1 = __half22float2(*(__half2*)&eus.y);

        float zf0 = fd0.x + fs0.x + ef0.x, zf1 = fd0.y + fs0.y + ef0.y;
        float zf2 = fd1.x + fs1.x + ef1.x, zf3 = fd1.y + fs1.y + ef1.y;
        float zs0 = sd0.x + ss0.x + es0.x, zs1 = sd0.y + ss0.y + es0.y;
        float zs2 = sd1.x + ss1.x + es1.x, zs3 = sd1.y + ss1.y + es1.y;

        float m0 = sigmoidf_(zf0) * softplusf_(zs0);
        float m1 = sigmoidf_(zf1) * softplusf_(zs1);
        float m2 = sigmoidf_(zf2) * softplusf_(zs2);
        float m3 = sigmoidf_(zf3) * softplusf_(zs3);

        float* ag = g_agg + (size_t)dst * HID + lane * 4;
        asm volatile("red.global.add.v4.f32 [%0], {%1,%2,%3,%4};"
                     :: "l"(ag), "f"(m0), "f"(m1), "f"(m2), "f"(m3) : "memory");
    }
}

// ---------------------------------------------------------------------------
// h = relu(h + agg); agg = 0
// ---------------------------------------------------------------------------
__global__ void k_update() {
    int idx = blockIdx.x * blockDim.x + threadIdx.x;  // NN*32
    if (idx >= NN * 32) return;
    float4 h = ((float4*)g_h)[idx];
    float4 a = ((float4*)g_agg)[idx];
    h.x = fmaxf(h.x + a.x, 0.f);
    h.y = fmaxf(h.y + a.y, 0.f);
    h.z = fmaxf(h.z + a.z, 0.f);
    h.w = fmaxf(h.w + a.w, 0.f);
    ((float4*)g_h)[idx] = h;
    ((float4*)g_agg)[idx] = make_float4(0.f, 0.f, 0.f, 0.f);
}

// ---------------------------------------------------------------------------
// pool: atomic sums per graph + counts
// ---------------------------------------------------------------------------
__global__ void k_pool(const int* __restrict__ batch) {
    int idx = blockIdx.x * blockDim.x + threadIdx.x;  // NN*32
    if (idx >= NN * 32) return;
    int n = idx >> 5, q = idx & 31;
    int g = batch[n];
    float4 v = ((float4*)g_h)[idx];
    float* p = g_pool + (size_t)g * HID + q * 4;
    asm volatile("red.global.add.v4.f32 [%0], {%1,%2,%3,%4};"
                 :: "l"(p), "f"(v.x), "f"(v.y), "f"(v.z), "f"(v.w) : "memory");
    if (q == 0) atomicAdd(&g_cnt[g], 1.f);
}

// ---------------------------------------------------------------------------
// final: out[g] = (pool[g]/max(cnt,1)) @ Wlin + blin   (block per graph)
// ---------------------------------------------------------------------------
__global__ void k_final(const float* __restrict__ Wlin, const float* __restrict__ blin,
                        float* __restrict__ out) {
    __shared__ float p[HID];
    int g = blockIdx.x, t = threadIdx.x;
    float c = fmaxf(g_cnt[g], 1.f);
    p[t] = g_pool[g * HID + t] / c;
    __syncthreads();
    float acc = blin[t];
#pragma unroll 8
    for (int k = 0; k < HID; k++) acc += p[k] * Wlin[k * HID + t];
    out[g * HID + t] = acc;
}

// ---------------------------------------------------------------------------
extern "C" void kernel_launch(void* const* d_in, const int* in_sizes, int n_in,
                              void* d_out, int out_size) {
    const int*   x    = (const int*)d_in[0];
    const int*   ei   = (const int*)d_in[1];
    const float* ea   = (const float*)d_in[2];
    const int*   batch= (const int*)d_in[3];
    const float* emb  = (const float*)d_in[4];
    const float* Wlin = (const float*)d_in[17];
    const float* blin = (const float*)d_in[18];

    float* out = (float*)d_out;

    __half* Pp;  cudaGetSymbolAddress((void**)&Pp, g_Ph);
    float*  hp;  cudaGetSymbolAddress((void**)&hp, g_h);

    static bool attr_done = false;
    if (!attr_done) {
        cudaFuncSetAttribute(k_fused, cudaFuncAttributeMaxDynamicSharedMemorySize,
                             SMEM_FUSED);
        attr_done = true;
    }

    // init
    {
        int total = NN * 32;
        k_init<<<(total + 255) / 256, 256>>>(x, emb);
    }

    for (int l = 0; l < 3; l++) {
        const float* Wf = (const float*)d_in[5 + 4 * l];
        const float* bf = (const float*)d_in[6 + 4 * l];
        const float* Ws = (const float*)d_in[7 + 4 * l];
        const float* bs = (const float*)d_in[8 + 4 * l];

        // Node projections: Ph[n] = [h@WfA+bf | h@WsA+bs | h@WfB | h@WsB] (fp16)
        {
            dim3 grid((NN + 127) / 128, 4);
            k_gemm_tc<<<grid, 256>>>(hp, NN,
                                     Wf, Ws, Wf + 128 * 128, Ws + 128 * 128,
                                     bf, bs, Pp, 512);
        }
        // Fused edge-attr projection + message + scatter
        {
            k_fused<<<NE / TILE_E, 256, SMEM_FUSED>>>(ei, ea,
                                                      Wf + 256 * 128, Ws + 256 * 128);
        }
        // h = relu(h + agg); agg = 0
        {
            int total = NN * 32;
            k_update<<<(total + 255) / 256, 256>>>();
        }
    }

    // pooling
    {
        int total = NN * 32;
        k_pool<<<(total + 255) / 256, 256>>>(batch);
    }
    // final linear
    k_final<<<NG, HID>>>(Wlin, blin, out);

    (void)in_sizes; (void)n_in; (void)out_size;
}

// round 8
// speedup vs baseline: 1.4025x; 1.2757x over previous
#include <cuda_runtime.h>
#include <cuda_fp16.h>
#include <cstdint>
#include <math.h>

#define NN 50000
#define NE 800000
#define HID 128
#define NG 500

// Scratch (device globals: no allocation allowed)
__device__ float g_h[(size_t)NN * HID];              // node features
__device__ __half g_Ph[(size_t)NN * 512];            // [Fdst|Sdst|Fsrc|Ssrc] per node (fp16)
__device__ float g_agg[(size_t)NN * HID];            // message aggregation
__device__ float g_pool[NG * HID];
__device__ float g_cnt[NG];

// ---------------------------------------------------------------------------
// helpers
// ---------------------------------------------------------------------------
__device__ __forceinline__ uint32_t f2tf32(float x) {
    uint32_t u;
    asm("cvt.rna.tf32.f32 %0, %1;" : "=r"(u) : "f"(x));
    return u;
}

__device__ __forceinline__ void mma_tf32(float c[4], const uint32_t a[4],
                                         const uint32_t b[2]) {
    asm volatile(
        "mma.sync.aligned.m16n8k8.row.col.f32.tf32.tf32.f32 "
        "{%0,%1,%2,%3}, {%4,%5,%6,%7}, {%8,%9}, {%0,%1,%2,%3};"
        : "+f"(c[0]), "+f"(c[1]), "+f"(c[2]), "+f"(c[3])
        : "r"(a[0]), "r"(a[1]), "r"(a[2]), "r"(a[3]), "r"(b[0]), "r"(b[1]));
}

// Fast activations: MUFU-based, no precise div / log1p polynomial.
__device__ __forceinline__ float sigmoidf_(float x) {
    return __fdividef(1.f, 1.f + __expf(-x));
}
__device__ __forceinline__ float softplusf_(float x) {
    // max(x,0) + log(1 + exp(-|x|)); __logf(1+t) abs-error negligible for t in (0,1]
    return fmaxf(x, 0.f) + __logf(1.f + __expf(-fabsf(x)));
}

// ---------------------------------------------------------------------------
// init: h = emb[x]; zero agg/pool/cnt
// ---------------------------------------------------------------------------
__global__ void k_init(const int* __restrict__ x, const float* __restrict__ emb) {
    int idx = blockIdx.x * blockDim.x + threadIdx.x;  // over NN*32 (float4 units)
    if (idx < NN * 32) {
        int n = idx >> 5, q = idx & 31;
        ((float4*)g_h)[idx] = ((const float4*)emb)[x[n] * 32 + q];
        ((float4*)g_agg)[idx] = make_float4(0.f, 0.f, 0.f, 0.f);
    }
    if (idx < NG * 32) ((float4*)g_pool)[idx] = make_float4(0.f, 0.f, 0.f, 0.f);
    if (idx < NG) g_cnt[idx] = 0.f;
}

// ---------------------------------------------------------------------------
// Node GEMM (tf32 mma m16n8k8): P[M,512] fp16 out, CTA tile 128x128,
// blockIdx.y = kind (0..3) selects weight slice + optional bias.
// ---------------------------------------------------------------------------
#define SSTR 136

__global__ void k_gemm_tc(const float* __restrict__ A, int M,
                          const float* __restrict__ W0, const float* __restrict__ W1,
                          const float* __restrict__ W2, const float* __restrict__ W3,
                          const float* __restrict__ b0, const float* __restrict__ b1,
                          __half* __restrict__ out, int ldo)
{
    __shared__ uint32_t Ast[16][SSTR];  // [k][m] transposed
    __shared__ uint32_t Bs[16][SSTR];   // [k][n]
    const int K = 128;

    int kind = blockIdx.y;
    const float* W = (kind == 0) ? W0 : (kind == 1) ? W1 : (kind == 2) ? W2 : W3;
    const float* bias = (kind == 0) ? b0 : (kind == 1) ? b1 : nullptr;
    int cb = kind * 128;
    int row0 = blockIdx.x * 128;
    int tid = threadIdx.x;           // 256 threads = 8 warps
    int lane = tid & 31, wid = tid >> 5;
    int wm = (wid & 1) * 64, wn = (wid >> 1) * 32;
    int gid4 = lane >> 2, tig = lane & 3;

    float acc[4][4][4];
#pragma unroll
    for (int i = 0; i < 4; i++)
#pragma unroll
        for (int j = 0; j < 4; j++)
#pragma unroll
            for (int r = 0; r < 4; r++) acc[i][j][r] = 0.f;

    for (int k0 = 0; k0 < K; k0 += 16) {
#pragma unroll
        for (int i = 0; i < 2; i++) {
            int id = tid * 2 + i;
            int r = id >> 2, q = (id & 3) * 4;
            float4 v = make_float4(0.f, 0.f, 0.f, 0.f);
            int gr = row0 + r;
            if (gr < M) v = *(const float4*)(A + (size_t)gr * K + k0 + q);
            Ast[q + 0][r] = f2tf32(v.x);
            Ast[q + 1][r] = f2tf32(v.y);
            Ast[q + 2][r] = f2tf32(v.z);
            Ast[q + 3][r] = f2tf32(v.w);
        }
#pragma unroll
        for (int i = 0; i < 2; i++) {
            int id = tid * 2 + i;
            int kk = id >> 5, n4 = (id & 31) * 4;
            float4 v = *(const float4*)(W + (size_t)(k0 + kk) * 128 + n4);
            Bs[kk][n4 + 0] = f2tf32(v.x);
            Bs[kk][n4 + 1] = f2tf32(v.y);
            Bs[kk][n4 + 2] = f2tf32(v.z);
            Bs[kk][n4 + 3] = f2tf32(v.w);
        }
        __syncthreads();

#pragma unroll
        for (int kk = 0; kk < 16; kk += 8) {
            uint32_t a[4][4], b[4][2];
#pragma unroll
            for (int i = 0; i < 4; i++) {
                int m0 = wm + i * 16 + gid4;
                a[i][0] = Ast[kk + tig][m0];
                a[i][1] = Ast[kk + tig][m0 + 8];
                a[i][2] = Ast[kk + tig + 4][m0];
                a[i][3] = Ast[kk + tig + 4][m0 + 8];
            }
#pragma unroll
            for (int j = 0; j < 4; j++) {
                int n0 = wn + j * 8 + gid4;
                b[j][0] = Bs[kk + tig][n0];
                b[j][1] = Bs[kk + tig + 4][n0];
            }
#pragma unroll
            for (int i = 0; i < 4; i++)
#pragma unroll
                for (int j = 0; j < 4; j++) mma_tf32(acc[i][j], a[i], b[j]);
        }
        __syncthreads();
    }

#pragma unroll
    for (int j = 0; j < 4; j++) {
        int cl = wn + j * 8 + 2 * tig;
        float bx = 0.f, by = 0.f;
        if (bias) { bx = bias[cl]; by = bias[cl + 1]; }
#pragma unroll
        for (int i = 0; i < 4; i++) {
            int r0 = row0 + wm + i * 16 + gid4;
            if (r0 < M)
                *(__half2*)(out + (size_t)r0 * ldo + cb + cl) =
                    __floats2half2_rn(acc[i][j][0] + bx, acc[i][j][1] + by);
            if (r0 + 8 < M)
                *(__half2*)(out + (size_t)(r0 + 8) * ldo + cb + cl) =
                    __floats2half2_rn(acc[i][j][2] + bx, acc[i][j][3] + by);
        }
    }
}

// ---------------------------------------------------------------------------
// Fused edge kernel: per CTA (256 thr), 64 edges.
//  Phase 1: Eproj[64x256] = ea[tile,32] @ [Wf_e | Ws_e] via tf32 mma -> smem fp16
//  Phase 2: warp-per-edge: z = Ph[dst] + Ph[src] + Eproj; msg; red.v4 to agg[dst]
// ---------------------------------------------------------------------------
#define TILE_E 64
#define ASTR2 72
#define BSTR2 264
#define ESTR 264

#define SMEM_FUSED (32 * ASTR2 * 4 + 32 * BSTR2 * 4 + TILE_E * ESTR * 2)

extern __shared__ unsigned char s_raw[];

__global__ void __launch_bounds__(256, 2)
k_fused(const int* __restrict__ ei, const float* __restrict__ ea,
        const float* __restrict__ Wfe, const float* __restrict__ Wse)
{
    uint32_t* Ast = (uint32_t*)s_raw;                 // [32][ASTR2]
    uint32_t* Bs  = Ast + 32 * ASTR2;                 // [32][BSTR2]
    __half* Ep = (__half*)(Bs + 32 * BSTR2);          // [64][ESTR]

    int e0 = blockIdx.x * TILE_E;
    int tid = threadIdx.x, lane = tid & 31, wid = tid >> 5;
    int gid4 = lane >> 2, tig = lane & 3;

    // ---- load A: ea[e0 .. e0+63][0:32] transposed -> Ast[k][m] ----
#pragma unroll
    for (int i = 0; i < 2; i++) {
        int id = tid * 2 + i;            // 0..511
        int r = id >> 3, q = (id & 7) * 4;
        float4 v = *(const float4*)(ea + (size_t)(e0 + r) * 32 + q);
        Ast[(q + 0) * ASTR2 + r] = f2tf32(v.x);
        Ast[(q + 1) * ASTR2 + r] = f2tf32(v.y);
        Ast[(q + 2) * ASTR2 + r] = f2tf32(v.z);
        Ast[(q + 3) * ASTR2 + r] = f2tf32(v.w);
    }
    // ---- load B: [32 x 256] = Wf_e cols | Ws_e cols ----
#pragma unroll
    for (int i = 0; i < 8; i++) {
        int id = tid + i * 256;          // 0..2047
        int kk = id >> 6, n4 = (id & 63) * 4;
        const float* src = (n4 < 128) ? (Wfe + kk * 128 + n4)
                                      : (Wse + kk * 128 + (n4 - 128));
        float4 v = *(const float4*)src;
        uint32_t* d = &Bs[kk * BSTR2 + n4];
        d[0] = f2tf32(v.x); d[1] = f2tf32(v.y);
        d[2] = f2tf32(v.z); d[3] = f2tf32(v.w);
    }
    __syncthreads();

    // ---- mma: M=64 (2 warp rows), N=256 (4 warp cols of 64), K=32 ----
    {
        int wm = (wid & 1) * 32, wn = (wid >> 1) * 64;
        float acc[2][8][4];
#pragma unroll
        for (int i = 0; i < 2; i++)
#pragma unroll
            for (int j = 0; j < 8; j++)
#pragma unroll
                for (int r = 0; r < 4; r++) acc[i][j][r] = 0.f;

#pragma unroll
        for (int kk = 0; kk < 32; kk += 8) {
            uint32_t a[2][4], b[8][2];
#pragma unroll
            for (int i = 0; i < 2; i++) {
                int m0 = wm + i * 16 + gid4;
                a[i][0] = Ast[(kk + tig) * ASTR2 + m0];
                a[i][1] = Ast[(kk + tig) * ASTR2 + m0 + 8];
                a[i][2] = Ast[(kk + tig + 4) * ASTR2 + m0];
                a[i][3] = Ast[(kk + tig + 4) * ASTR2 + m0 + 8];
            }
#pragma unroll
            for (int j = 0; j < 8; j++) {
                int n0 = wn + j * 8 + gid4;
                b[j][0] = Bs[(kk + tig) * BSTR2 + n0];
                b[j][1] = Bs[(kk + tig + 4) * BSTR2 + n0];
            }
#pragma unroll
            for (int i = 0; i < 2; i++)
#pragma unroll
                for (int j = 0; j < 8; j++) mma_tf32(acc[i][j], a[i], b[j]);
        }

        // write Eproj (fp16x2)
#pragma unroll
        for (int j = 0; j < 8; j++) {
            int cl = wn + j * 8 + 2 * tig;
#pragma unroll
            for (int i = 0; i < 2; i++) {
                int row = wm + i * 16 + gid4;
                *(__half2*)&Ep[row * ESTR + cl] =
                    __floats2half2_rn(acc[i][j][0], acc[i][j][1]);
                *(__half2*)&Ep[(row + 8) * ESTR + cl] =
                    __floats2half2_rn(acc[i][j][2], acc[i][j][3]);
            }
        }
    }
    __syncthreads();

    // ---- edge phase: warp wid handles edges wid*8 .. wid*8+7 ----
#pragma unroll 2
    for (int t = 0; t < 8; t++) {
        int el = wid * 8 + t;
        int e = e0 + el;
        int src = ei[e];
        int dst = ei[NE + e];

        // uint2 = 4 halves per lane; layout in halves:
        // [0:128)=Fdst [128:256)=Sdst [256:384)=Fsrc [384:512)=Ssrc
        const uint2* pd = (const uint2*)(g_Ph + (size_t)dst * 512);
        const uint2* ps = (const uint2*)(g_Ph + (size_t)src * 512);

        uint2 fdu = pd[lane],      sdu = pd[lane + 32];
        uint2 fsu = ps[lane + 64], ssu = ps[lane + 96];

        float2 fd0 = __half22float2(*(__half2*)&fdu.x);
        float2 fd1 = __half22float2(*(__half2*)&fdu.y);
        float2 sd0 = __half22float2(*(__half2*)&sdu.x);
        float2 sd1 = __half22float2(*(__half2*)&sdu.y);
        float2 fs0 = __half22float2(*(__half2*)&fsu.x);
        float2 fs1 = __half22float2(*(__half2*)&fsu.y);
        float2 ss0 = __half22float2(*(__half2*)&ssu.x);
        float2 ss1 = __half22float2(*(__half2*)&ssu.y);

        uint2 euf = *(const uint2*)&Ep[el * ESTR + lane * 4];
        uint2 eus = *(const uint2*)&Ep[el * ESTR + 128 + lane * 4];
        float2 ef0 = __half22float2(*(__half2*)&euf.x);
        float2 ef1 = __half22float2(*(__half2*)&euf.y);
        float2 es0 = __half22float2(*(__half2*)&eus.x);
        float2 es1 = __half22float2(*(__half2*)&eus.y);

        float zf0 = fd0.x + fs0.x + ef0.x, zf1 = fd0.y + fs0.y + ef0.y;
        float zf2 = fd1.x + fs1.x + ef1.x, zf3 = fd1.y + fs1.y + ef1.y;
        float zs0 = sd0.x + ss0.x + es0.x, zs1 = sd0.y + ss0.y + es0.y;
        float zs2 = sd1.x + ss1.x + es1.x, zs3 = sd1.y + ss1.y + es1.y;

        float m0 = sigmoidf_(zf0) * softplusf_(zs0);
        float m1 = sigmoidf_(zf1) * softplusf_(zs1);
        float m2 = sigmoidf_(zf2) * softplusf_(zs2);
        float m3 = sigmoidf_(zf3) * softplusf_(zs3);

        float* ag = g_agg + (size_t)dst * HID + lane * 4;
        asm volatile("red.global.add.v4.f32 [%0], {%1,%2,%3,%4};"
                     :: "l"(ag), "f"(m0), "f"(m1), "f"(m2), "f"(m3) : "memory");
    }
}

// ---------------------------------------------------------------------------
// h = relu(h + agg); agg = 0
// ---------------------------------------------------------------------------
__global__ void k_update() {
    int idx = blockIdx.x * blockDim.x + threadIdx.x;  // NN*32
    if (idx >= NN * 32) return;
    float4 h = ((float4*)g_h)[idx];
    float4 a = ((float4*)g_agg)[idx];
    h.x = fmaxf(h.x + a.x, 0.f);
    h.y = fmaxf(h.y + a.y, 0.f);
    h.z = fmaxf(h.z + a.z, 0.f);
    h.w = fmaxf(h.w + a.w, 0.f);
    ((float4*)g_h)[idx] = h;
    ((float4*)g_agg)[idx] = make_float4(0.f, 0.f, 0.f, 0.f);
}

// ---------------------------------------------------------------------------
// pool: atomic sums per graph + counts
// ---------------------------------------------------------------------------
__global__ void k_pool(const int* __restrict__ batch) {
    int idx = blockIdx.x * blockDim.x + threadIdx.x;  // NN*32
    if (idx >= NN * 32) return;
    int n = idx >> 5, q = idx & 31;
    int g = batch[n];
    float4 v = ((float4*)g_h)[idx];
    float* p = g_pool + (size_t)g * HID + q * 4;
    asm volatile("red.global.add.v4.f32 [%0], {%1,%2,%3,%4};"
                 :: "l"(p), "f"(v.x), "f"(v.y), "f"(v.z), "f"(v.w) : "memory");
    if (q == 0) atomicAdd(&g_cnt[g], 1.f);
}

// ---------------------------------------------------------------------------
// final: out[g] = (pool[g]/max(cnt,1)) @ Wlin + blin   (block per graph)
// ---------------------------------------------------------------------------
__global__ void k_final(const float* __restrict__ Wlin, const float* __restrict__ blin,
                        float* __restrict__ out) {
    __shared__ float p[HID];
    int g = blockIdx.x, t = threadIdx.x;
    float c = fmaxf(g_cnt[g], 1.f);
    p[t] = g_pool[g * HID + t] / c;
    __syncthreads();
    float acc = blin[t];
#pragma unroll 8
    for (int k = 0; k < HID; k++) acc += p[k] * Wlin[k * HID + t];
    out[g * HID + t] = acc;
}

// ---------------------------------------------------------------------------
extern "C" void kernel_launch(void* const* d_in, const int* in_sizes, int n_in,
                              void* d_out, int out_size) {
    const int*   x    = (const int*)d_in[0];
    const int*   ei   = (const int*)d_in[1];
    const float* ea   = (const float*)d_in[2];
    const int*   batch= (const int*)d_in[3];
    const float* emb  = (const float*)d_in[4];
    const float* Wlin = (const float*)d_in[17];
    const float* blin = (const float*)d_in[18];

    float* out = (float*)d_out;

    __half* Pp;  cudaGetSymbolAddress((void**)&Pp, g_Ph);
    float*  hp;  cudaGetSymbolAddress((void**)&hp, g_h);

    static bool attr_done = false;
    if (!attr_done) {
        cudaFuncSetAttribute(k_fused, cudaFuncAttributeMaxDynamicSharedMemorySize,
                             SMEM_FUSED);
        attr_done = true;
    }

    // init
    {
        int total = NN * 32;
        k_init<<<(total + 255) / 256, 256>>>(x, emb);
    }

    for (int l = 0; l < 3; l++) {
        const float* Wf = (const float*)d_in[5 + 4 * l];
        const float* bf = (const float*)d_in[6 + 4 * l];
        const float* Ws = (const float*)d_in[7 + 4 * l];
        const float* bs = (const float*)d_in[8 + 4 * l];

        // Node projections: Ph[n] = [h@WfA+bf | h@WsA+bs | h@WfB | h@WsB] (fp16)
        {
            dim3 grid((NN + 127) / 128, 4);
            k_gemm_tc<<<grid, 256>>>(hp, NN,
                                     Wf, Ws, Wf + 128 * 128, Ws + 128 * 128,
                                     bf, bs, Pp, 512);
        }
        // Fused edge-attr projection + message + scatter
        {
            k_fused<<<NE / TILE_E, 256, SMEM_FUSED>>>(ei, ea,
                                                      Wf + 256 * 128, Ws + 256 * 128);
        }
        // h = relu(h + agg); agg = 0
        {
            int total = NN * 32;
            k_update<<<(total + 255) / 256, 256>>>();
        }
    }

    // pooling
    {
        int total = NN * 32;
        k_pool<<<(total + 255) / 256, 256>>>(batch);
    }
    // final linear
    k_final<<<NG, HID>>>(Wlin, blin, out);

    (void)in_sizes; (void)n_in; (void)out_size;
}

// round 12
// speedup vs baseline: 1.4563x; 1.0384x over previous
#include <cuda_runtime.h>
#include <cuda_fp16.h>
#include <cstdint>
#include <math.h>

#define NN 50000
#define NE 800000
#define HID 128
#define NG 500

// Scratch (device globals: no allocation allowed)
__device__ float g_h[(size_t)NN * HID];              // node features
__device__ __half g_Ph[(size_t)NN * 512];            // [Fdst|Sdst|Fsrc|Ssrc] per node (fp16)
__device__ float g_agg[(size_t)NN * HID];            // message aggregation
__device__ float g_pool[NG * HID];
__device__ float g_cnt[NG];

// ---------------------------------------------------------------------------
// helpers
// ---------------------------------------------------------------------------
__device__ __forceinline__ uint32_t f2tf32(float x) {
    uint32_t u;
    asm("cvt.rna.tf32.f32 %0, %1;" : "=r"(u) : "f"(x));
    return u;
}

__device__ __forceinline__ void mma_tf32(float c[4], const uint32_t a[4],
                                         const uint32_t b[2]) {
    asm volatile(
        "mma.sync.aligned.m16n8k8.row.col.f32.tf32.tf32.f32 "
        "{%0,%1,%2,%3}, {%4,%5,%6,%7}, {%8,%9}, {%0,%1,%2,%3};"
        : "+f"(c[0]), "+f"(c[1]), "+f"(c[2]), "+f"(c[3])
        : "r"(a[0]), "r"(a[1]), "r"(a[2]), "r"(a[3]), "r"(b[0]), "r"(b[1]));
}

// Fast activations (MUFU-based)
__device__ __forceinline__ float sigmoidf_(float x) {
    return __fdividef(1.f, 1.f + __expf(-x));
}
__device__ __forceinline__ float softplusf_(float x) {
    return fmaxf(x, 0.f) + __logf(1.f + __expf(-fabsf(x)));
}

// ---------------------------------------------------------------------------
// init: h = emb[x]; zero agg/pool/cnt
// ---------------------------------------------------------------------------
__global__ void k_init(const int* __restrict__ x, const float* __restrict__ emb) {
    int idx = blockIdx.x * blockDim.x + threadIdx.x;  // over NN*32 (float4 units)
    if (idx < NN * 32) {
        int n = idx >> 5, q = idx & 31;
        ((float4*)g_h)[idx] = ((const float4*)emb)[x[n] * 32 + q];
        ((float4*)g_agg)[idx] = make_float4(0.f, 0.f, 0.f, 0.f);
    }
    if (idx < NG * 32) ((float4*)g_pool)[idx] = make_float4(0.f, 0.f, 0.f, 0.f);
    if (idx < NG) g_cnt[idx] = 0.f;
}

// ---------------------------------------------------------------------------
// Node GEMM, all 4 kinds per CTA: Ph[row0:row0+128][0:512].
// A (h rows, optionally fused with relu-update from agg) staged once in smem;
// B streamed in 32-k slabs via reg-prefetch + double-buffered smem.
//  kind0: h @ Wf[0:128]  + bf   kind1: h @ Ws[0:128] + bs
//  kind2: h @ Wf[128:256]       kind3: h @ Ws[128:256]
// ---------------------------------------------------------------------------
#define ASTR3 136
#define BSTR3 136
#define SMEM_GEMM ((128 * ASTR3 + 2 * 32 * BSTR3) * 4)   // 104448 B

extern __shared__ unsigned char s_raw[];

__global__ void __launch_bounds__(256, 2)
k_gemm_all(float* __restrict__ Ah, float* __restrict__ Agg, int fuse,
           const float* __restrict__ Wf, const float* __restrict__ Ws,
           const float* __restrict__ bf, const float* __restrict__ bs,
           __half* __restrict__ out)
{
    uint32_t* Ast = (uint32_t*)s_raw;          // [128 m][ASTR3] (k-major rows)
    uint32_t* Bs  = Ast + 128 * ASTR3;         // [2][32 k][BSTR3]

    int row0 = blockIdx.x * 128;
    int tid = threadIdx.x;                     // 256 threads = 8 warps
    int lane = tid & 31, wid = tid >> 5;
    int wm = (wid & 1) * 64, wn = (wid >> 1) * 32;
    int gid4 = lane >> 2, tig = lane & 3;

    // ---- B slab prefetch machinery ----
    float4 pre[4];
    auto fetch = [&](int iter) {
        int kind = iter >> 2, slab = iter & 3;
        const float* W = (kind & 1) ? Ws : Wf;
        const float* base = W + (size_t)(((kind >> 1) ? 128 : 0) + slab * 32) * 128;
#pragma unroll
        for (int i = 0; i < 4; i++) {
            int id = tid + i * 256;            // float4 over 32k x 32
            int kk = id >> 5, c4 = (id & 31) * 4;
            pre[i] = *(const float4*)(base + kk * 128 + c4);
        }
    };
    auto commit = [&](int buf) {
#pragma unroll
        for (int i = 0; i < 4; i++) {
            int id = tid + i * 256;
            int kk = id >> 5, c4 = (id & 31) * 4;
            uint32_t* d = &Bs[(buf * 32 + kk) * BSTR3 + c4];
            d[0] = f2tf32(pre[i].x); d[1] = f2tf32(pre[i].y);
            d[2] = f2tf32(pre[i].z); d[3] = f2tf32(pre[i].w);
        }
    };

    fetch(0);

    // ---- stage A: 128 rows x 128 k; optional fused relu-update ----
#pragma unroll
    for (int i = 0; i < 16; i++) {
        int id = tid + i * 256;                // float4 over 128 rows x 32
        int r = id >> 5, c4 = (id & 31) * 4;
        int gr = row0 + r;
        float4 v = make_float4(0.f, 0.f, 0.f, 0.f);
        if (gr < NN) {
            v = *(const float4*)(Ah + (size_t)gr * HID + c4);
            if (fuse) {
                float4 a = *(const float4*)(Agg + (size_t)gr * HID + c4);
                v.x = fmaxf(v.x + a.x, 0.f);
                v.y = fmaxf(v.y + a.y, 0.f);
                v.z = fmaxf(v.z + a.z, 0.f);
                v.w = fmaxf(v.w + a.w, 0.f);
                *(float4*)(Ah + (size_t)gr * HID + c4) = v;
                *(float4*)(Agg + (size_t)gr * HID + c4) = make_float4(0.f, 0.f, 0.f, 0.f);
            }
        }
        *(uint4*)&Ast[r * ASTR3 + c4] =
            make_uint4(f2tf32(v.x), f2tf32(v.y), f2tf32(v.z), f2tf32(v.w));
    }

    commit(0);
    __syncthreads();

    float acc[4][4][4];
#pragma unroll
    for (int i = 0; i < 4; i++)
#pragma unroll
        for (int j = 0; j < 4; j++)
#pragma unroll
            for (int r = 0; r < 4; r++) acc[i][j][r] = 0.f;

    for (int iter = 0; iter < 16; iter++) {
        if (iter < 15) fetch(iter + 1);
        int buf = iter & 1;
        int kbase = (iter & 3) * 32;     // <<< FIX: A's k-offset for this slab

        // compute this 32-k slab
#pragma unroll
        for (int kk = 0; kk < 32; kk += 8) {
            uint32_t a[4][4], b[4][2];
#pragma unroll
            for (int i = 0; i < 4; i++) {
                int m0 = wm + i * 16 + gid4;
                const uint32_t* r0p = &Ast[m0 * ASTR3 + kbase + kk + tig];
                const uint32_t* r1p = &Ast[(m0 + 8) * ASTR3 + kbase + kk + tig];
                a[i][0] = r0p[0];
                a[i][1] = r1p[0];
                a[i][2] = r0p[4];
                a[i][3] = r1p[4];
            }
#pragma unroll
            for (int j = 0; j < 4; j++) {
                int n0 = wn + j * 8 + gid4;
                b[j][0] = Bs[(buf * 32 + kk + tig) * BSTR3 + n0];
                b[j][1] = Bs[(buf * 32 + kk + tig + 4) * BSTR3 + n0];
            }
#pragma unroll
            for (int i = 0; i < 4; i++)
#pragma unroll
                for (int j = 0; j < 4; j++) mma_tf32(acc[i][j], a[i], b[j]);
        }

        // end of a kind (4 slabs) -> epilogue
        if ((iter & 3) == 3) {
            int kind = iter >> 2;
            const float* bias = (kind == 0) ? bf : (kind == 1) ? bs : nullptr;
            int cb = kind * 128;
#pragma unroll
            for (int j = 0; j < 4; j++) {
                int cl = wn + j * 8 + 2 * tig;
                float bx = 0.f, by = 0.f;
                if (bias) { bx = bias[cl]; by = bias[cl + 1]; }
#pragma unroll
                for (int i = 0; i < 4; i++) {
                    int r0 = row0 + wm + i * 16 + gid4;
                    if (r0 < NN)
                        *(__half2*)(out + (size_t)r0 * 512 + cb + cl) =
                            __floats2half2_rn(acc[i][j][0] + bx, acc[i][j][1] + by);
                    if (r0 + 8 < NN)
                        *(__half2*)(out + (size_t)(r0 + 8) * 512 + cb + cl) =
                            __floats2half2_rn(acc[i][j][2] + bx, acc[i][j][3] + by);
                }
            }
#pragma unroll
            for (int i = 0; i < 4; i++)
#pragma unroll
                for (int j = 0; j < 4; j++)
#pragma unroll
                    for (int r = 0; r < 4; r++) acc[i][j][r] = 0.f;
        }

        if (iter < 15) {
            __syncthreads();            // all compute on old buf done
            commit((iter + 1) & 1);     // fill other buffer
            __syncthreads();            // visible before next compute
        }
    }
}

// ---------------------------------------------------------------------------
// Fused edge kernel: per CTA (256 thr), 64 edges.
//  Phase 1: Eproj[64x256] = ea[tile,32] @ [Wf_e | Ws_e] via tf32 mma -> smem fp16
//  Phase 2: warp-per-edge: z = Ph[dst] + Ph[src] + Eproj; msg; red.v4 to agg[dst]
// ---------------------------------------------------------------------------
#define TILE_E 64
#define ASTR2 72
#define BSTR2 264
#define ESTR 264

#define SMEM_FUSED (32 * ASTR2 * 4 + 32 * BSTR2 * 4 + TILE_E * ESTR * 2)

__global__ void __launch_bounds__(256, 2)
k_fused(const int* __restrict__ ei, const float* __restrict__ ea,
        const float* __restrict__ Wfe, const float* __restrict__ Wse)
{
    uint32_t* Ast = (uint32_t*)s_raw;                 // [32][ASTR2]
    uint32_t* Bs  = Ast + 32 * ASTR2;                 // [32][BSTR2]
    __half* Ep = (__half*)(Bs + 32 * BSTR2);          // [64][ESTR]

    int e0 = blockIdx.x * TILE_E;
    int tid = threadIdx.x, lane = tid & 31, wid = tid >> 5;
    int gid4 = lane >> 2, tig = lane & 3;

    // ---- load A: ea[e0 .. e0+63][0:32] transposed -> Ast[k][m] ----
#pragma unroll
    for (int i = 0; i < 2; i++) {
        int id = tid * 2 + i;            // 0..511
        int r = id >> 3, q = (id & 7) * 4;
        float4 v = *(const float4*)(ea + (size_t)(e0 + r) * 32 + q);
        Ast[(q + 0) * ASTR2 + r] = f2tf32(v.x);
        Ast[(q + 1) * ASTR2 + r] = f2tf32(v.y);
        Ast[(q + 2) * ASTR2 + r] = f2tf32(v.z);
        Ast[(q + 3) * ASTR2 + r] = f2tf32(v.w);
    }
    // ---- load B: [32 x 256] = Wf_e cols | Ws_e cols ----
#pragma unroll
    for (int i = 0; i < 8; i++) {
        int id = tid + i * 256;          // 0..2047
        int kk = id >> 6, n4 = (id & 63) * 4;
        const float* src = (n4 < 128) ? (Wfe + kk * 128 + n4)
                                      : (Wse + kk * 128 + (n4 - 128));
        float4 v = *(const float4*)src;
        uint32_t* d = &Bs[kk * BSTR2 + n4];
        d[0] = f2tf32(v.x); d[1] = f2tf32(v.y);
        d[2] = f2tf32(v.z); d[3] = f2tf32(v.w);
    }
    __syncthreads();

    // ---- mma: M=64 (2 warp rows), N=256 (4 warp cols of 64), K=32 ----
    {
        int wm = (wid & 1) * 32, wn = (wid >> 1) * 64;
        float acc[2][8][4];
#pragma unroll
        for (int i = 0; i < 2; i++)
#pragma unroll
            for (int j = 0; j < 8; j++)
#pragma unroll
                for (int r = 0; r < 4; r++) acc[i][j][r] = 0.f;

#pragma unroll
        for (int kk = 0; kk < 32; kk += 8) {
            uint32_t a[2][4], b[8][2];
#pragma unroll
            for (int i = 0; i < 2; i++) {
                int m0 = wm + i * 16 + gid4;
                a[i][0] = Ast[(kk + tig) * ASTR2 + m0];
                a[i][1] = Ast[(kk + tig) * ASTR2 + m0 + 8];
                a[i][2] = Ast[(kk + tig + 4) * ASTR2 + m0];
                a[i][3] = Ast[(kk + tig + 4) * ASTR2 + m0 + 8];
            }
#pragma unroll
            for (int j = 0; j < 8; j++) {
                int n0 = wn + j * 8 + gid4;
                b[j][0] = Bs[(kk + tig) * BSTR2 + n0];
                b[j][1] = Bs[(kk + tig + 4) * BSTR2 + n0];
            }
#pragma unroll
            for (int i = 0; i < 2; i++)
#pragma unroll
                for (int j = 0; j < 8; j++) mma_tf32(acc[i][j], a[i], b[j]);
        }

        // write Eproj (fp16x2)
#pragma unroll
        for (int j = 0; j < 8; j++) {
            int cl = wn + j * 8 + 2 * tig;
#pragma unroll
            for (int i = 0; i < 2; i++) {
                int row = wm + i * 16 + gid4;
                *(__half2*)&Ep[row * ESTR + cl] =
                    __floats2half2_rn(acc[i][j][0], acc[i][j][1]);
                *(__half2*)&Ep[(row + 8) * ESTR + cl] =
                    __floats2half2_rn(acc[i][j][2], acc[i][j][3]);
            }
        }
    }
    __syncthreads();

    // ---- edge phase: warp wid handles edges wid*8 .. wid*8+7 ----
#pragma unroll 2
    for (int t = 0; t < 8; t++) {
        int el = wid * 8 + t;
        int e = e0 + el;
        int src = ei[e];
        int dst = ei[NE + e];

        const uint2* pd = (const uint2*)(g_Ph + (size_t)dst * 512);
        const uint2* ps = (const uint2*)(g_Ph + (size_t)src * 512);

        uint2 fdu = pd[lane],      sdu = pd[lane + 32];
        uint2 fsu = ps[lane + 64], ssu = ps[lane + 96];

        float2 fd0 = __half22float2(*(__half2*)&fdu.x);
        float2 fd1 = __half22float2(*(__half2*)&fdu.y);
        float2 sd0 = __half22float2(*(__half2*)&sdu.x);
        float2 sd1 = __half22float2(*(__half2*)&sdu.y);
        float2 fs0 = __half22float2(*(__half2*)&fsu.x);
        float2 fs1 = __half22float2(*(__half2*)&fsu.y);
        float2 ss0 = __half22float2(*(__half2*)&ssu.x);
        float2 ss1 = __half22float2(*(__half2*)&ssu.y);

        uint2 euf = *(const uint2*)&Ep[el * ESTR + lane * 4];
        uint2 eus = *(const uint2*)&Ep[el * ESTR + 128 + lane * 4];
        float2 ef0 = __half22float2(*(__half2*)&euf.x);
        float2 ef1 = __half22float2(*(__half2*)&euf.y);
        float2 es0 = __half22float2(*(__half2*)&eus.x);
        float2 es1 = __half22float2(*(__half2*)&eus.y);

        float zf0 = fd0.x + fs0.x + ef0.x, zf1 = fd0.y + fs0.y + ef0.y;
        float zf2 = fd1.x + fs1.x + ef1.x, zf3 = fd1.y + fs1.y + ef1.y;
        float zs0 = sd0.x + ss0.x + es0.x, zs1 = sd0.y + ss0.y + es0.y;
        float zs2 = sd1.x + ss1.x + es1.x, zs3 = sd1.y + ss1.y + es1.y;

        float m0 = sigmoidf_(zf0) * softplusf_(zs0);
        float m1 = sigmoidf_(zf1) * softplusf_(zs1);
        float m2 = sigmoidf_(zf2) * softplusf_(zs2);
        float m3 = sigmoidf_(zf3) * softplusf_(zs3);

        float* ag = g_agg + (size_t)dst * HID + lane * 4;
        asm volatile("red.global.add.v4.f32 [%0], {%1,%2,%3,%4};"
                     :: "l"(ag), "f"(m0), "f"(m1), "f"(m2), "f"(m3) : "memory");
    }
}

// ---------------------------------------------------------------------------
// pool: v = relu(h + agg) (last layer's update folded in); atomic sums + counts
// ---------------------------------------------------------------------------
__global__ void k_pool(const int* __restrict__ batch) {
    int idx = blockIdx.x * blockDim.x + threadIdx.x;  // NN*32
    if (idx >= NN * 32) return;
    int n = idx >> 5, q = idx & 31;
    int g = batch[n];
    float4 h = ((float4*)g_h)[idx];
    float4 a = ((float4*)g_agg)[idx];
    float vx = fmaxf(h.x + a.x, 0.f), vy = fmaxf(h.y + a.y, 0.f);
    float vz = fmaxf(h.z + a.z, 0.f), vw = fmaxf(h.w + a.w, 0.f);
    float* p = g_pool + (size_t)g * HID + q * 4;
    asm volatile("red.global.add.v4.f32 [%0], {%1,%2,%3,%4};"
                 :: "l"(p), "f"(vx), "f"(vy), "f"(vz), "f"(vw) : "memory");
    if (q == 0) atomicAdd(&g_cnt[g], 1.f);
}

// ---------------------------------------------------------------------------
// final: out[g] = (pool[g]/max(cnt,1)) @ Wlin + blin   (block per graph)
// ---------------------------------------------------------------------------
__global__ void k_final(const float* __restrict__ Wlin, const float* __restrict__ blin,
                        float* __restrict__ out) {
    __shared__ float p[HID];
    int g = blockIdx.x, t = threadIdx.x;
    float c = fmaxf(g_cnt[g], 1.f);
    p[t] = g_pool[g * HID + t] / c;
    __syncthreads();
    float acc = blin[t];
#pragma unroll 8
    for (int k = 0; k < HID; k++) acc += p[k] * Wlin[k * HID + t];
    out[g * HID + t] = acc;
}

// ---------------------------------------------------------------------------
extern "C" void kernel_launch(void* const* d_in, const int* in_sizes, int n_in,
                              void* d_out, int out_size) {
    const int*   x    = (const int*)d_in[0];
    const int*   ei   = (const int*)d_in[1];
    const float* ea   = (const float*)d_in[2];
    const int*   batch= (const int*)d_in[3];
    const float* emb  = (const float*)d_in[4];
    const float* Wlin = (const float*)d_in[17];
    const float* blin = (const float*)d_in[18];

    float* out = (float*)d_out;

    __half* Pp;   cudaGetSymbolAddress((void**)&Pp, g_Ph);
    float*  hp;   cudaGetSymbolAddress((void**)&hp, g_h);
    float*  aggp; cudaGetSymbolAddress((void**)&aggp, g_agg);

    static bool attr_done = false;
    if (!attr_done) {
        cudaFuncSetAttribute(k_fused, cudaFuncAttributeMaxDynamicSharedMemorySize,
                             SMEM_FUSED);
        cudaFuncSetAttribute(k_gemm_all, cudaFuncAttributeMaxDynamicSharedMemorySize,
                             SMEM_GEMM);
        attr_done = true;
    }

    // init
    {
        int total = NN * 32;
        k_init<<<(total + 255) / 256, 256>>>(x, emb);
    }

    for (int l = 0; l < 3; l++) {
        const float* Wf = (const float*)d_in[5 + 4 * l];
        const float* bf = (const float*)d_in[6 + 4 * l];
        const float* Ws = (const float*)d_in[7 + 4 * l];
        const float* bs = (const float*)d_in[8 + 4 * l];

        // Node projections (all 4 kinds per CTA); layers 2,3 fuse the relu-update
        {
            int grid = (NN + 127) / 128;  // 391
            k_gemm_all<<<grid, 256, SMEM_GEMM>>>(hp, aggp, (l > 0) ? 1 : 0,
                                                 Wf, Ws, bf, bs, Pp);
        }
        // Fused edge-attr projection + message + scatter
        {
            k_fused<<<NE / TILE_E, 256, SMEM_FUSED>>>(ei, ea,
                                                      Wf + 256 * 128, Ws + 256 * 128);
        }
    }

    // pooling (includes last layer's relu-update)
    {
        int total = NN * 32;
        k_pool<<<(total + 255) / 256, 256>>>(batch);
    }
    // final linear
    k_final<<<NG, HID>>>(Wlin, blin, out);

    (void)in_sizes; (void)n_in; (void)out_size;
}